// round 12
// baseline (speedup 1.0000x reference)
#include <cuda_runtime.h>
#include <cuda_bf16.h>
#include <math.h>
#include <stdint.h>

#define NPTS 8192
#define EPSV 1e-5f

// fp32 scratch
__device__ float d_h1[NPTS * 64];
__device__ float d_h2[NPTS * 256];
__device__ int   d_knn[NPTS * 8];
__device__ float d_G[NPTS * 1024];
__device__ float d_C[NPTS * 1024];
__device__ float d_ymax[NPTS * 1024];
__device__ float d_ymin[NPTS * 1024];
__device__ float d_sum[6 * 1024];
__device__ float d_sq[6 * 1024];
__device__ float d_scale[6 * 1024];
__device__ float d_shift[6 * 1024];
// split-bf16 operands
__device__ __nv_bfloat16 d_h2h[NPTS * 256],  d_h2l[NPTS * 256];
__device__ __nv_bfloat16 d_lAh[NPTS * 512],  d_lAl[NPTS * 512];
__device__ __nv_bfloat16 d_wA1h[1024 * 256], d_wA1l[1024 * 256];
__device__ __nv_bfloat16 d_wB1h[2048 * 512], d_wB1l[2048 * 512];
__device__ __nv_bfloat16 d_wA2h[512 * 512],  d_wA2l[512 * 512];
__device__ __nv_bfloat16 d_wB2h[1024 * 1024], d_wB2l[1024 * 1024];

// ---------------- helpers ----------------------------------------------------
__device__ __forceinline__ uint32_t s2u(const void* p) {
    uint32_t a;
    asm("{ .reg .u64 t; cvta.to.shared.u64 t, %1; cvt.u32.u64 %0, t; }"
        : "=r"(a) : "l"(p));
    return a;
}
__device__ __forceinline__ void ldsm4(uint32_t* r, uint32_t a) {
    asm volatile("ldmatrix.sync.aligned.m8n8.x4.shared.b16 {%0,%1,%2,%3}, [%4];"
                 : "=r"(r[0]), "=r"(r[1]), "=r"(r[2]), "=r"(r[3]) : "r"(a));
}
__device__ __forceinline__ void mma16816(float* c, const uint32_t* a, const uint32_t* b) {
    asm volatile(
        "mma.sync.aligned.m16n8k16.row.col.f32.bf16.bf16.f32 "
        "{%0,%1,%2,%3}, {%4,%5,%6,%7}, {%8,%9}, {%0,%1,%2,%3};"
        : "+f"(c[0]), "+f"(c[1]), "+f"(c[2]), "+f"(c[3])
        : "r"(a[0]), "r"(a[1]), "r"(a[2]), "r"(a[3]), "r"(b[0]), "r"(b[1]));
}
__device__ __forceinline__ void cpa16(uint32_t dst, const void* src) {
    asm volatile("cp.async.cg.shared.global [%0], [%1], 16;" :: "r"(dst), "l"(src));
}
#define CP_COMMIT() asm volatile("cp.async.commit_group;" ::: "memory")
#define CP_WAIT1() asm volatile("cp.async.wait_group 1;" ::: "memory")
#define CP_WAIT0() asm volatile("cp.async.wait_group 0;" ::: "memory")

__device__ __forceinline__ float bflymax(float v) {
    v = fmaxf(v, __shfl_xor_sync(0xffffffffu, v, 4));
    v = fmaxf(v, __shfl_xor_sync(0xffffffffu, v, 8));
    v = fmaxf(v, __shfl_xor_sync(0xffffffffu, v, 16));
    return v;
}
__device__ __forceinline__ float bflymin(float v) {
    v = fminf(v, __shfl_xor_sync(0xffffffffu, v, 4));
    v = fminf(v, __shfl_xor_sync(0xffffffffu, v, 8));
    v = fminf(v, __shfl_xor_sync(0xffffffffu, v, 16));
    return v;
}
__device__ __forceinline__ float bflyadd(float v) {
    v += __shfl_xor_sync(0xffffffffu, v, 4);
    v += __shfl_xor_sync(0xffffffffu, v, 8);
    v += __shfl_xor_sync(0xffffffffu, v, 16);
    return v;
}

__device__ __forceinline__ void split_pack8(const float* v, uint4& h, uint4& l) {
    uint32_t hh[4], ll[4];
#pragma unroll
    for (int i = 0; i < 4; i++) {
        __nv_bfloat162 hp = __floats2bfloat162_rn(v[2 * i], v[2 * i + 1]);
        float r0 = v[2 * i] - __bfloat162float(__low2bfloat16(hp));
        float r1 = v[2 * i + 1] - __bfloat162float(__high2bfloat16(hp));
        __nv_bfloat162 lp = __floats2bfloat162_rn(r0, r1);
        hh[i] = reinterpret_cast<uint32_t&>(hp);
        ll[i] = reinterpret_cast<uint32_t&>(lp);
    }
    h = make_uint4(hh[0], hh[1], hh[2], hh[3]);
    l = make_uint4(ll[0], ll[1], ll[2], ll[3]);
}
// BN+ReLU+split: g may point into SMEM (generic loads)
__device__ __forceinline__ void fill_bn(const float* g, const float* __restrict__ c,
                                        const float* sc, const float* sh,
                                        char* hi, char* lo, uint32_t bo) {
#pragma unroll
    for (int j = 0; j < 32; j += 8) {
        float gv[8], cv[8], scv[8], shv[8], v[8];
        *(float4*)gv        = *(const float4*)(g + j);
        *(float4*)(gv + 4)  = *(const float4*)(g + j + 4);
        *(float4*)cv        = *(const float4*)(c + j);
        *(float4*)(cv + 4)  = *(const float4*)(c + j + 4);
        *(float4*)scv       = *(const float4*)(sc + j);
        *(float4*)(scv + 4) = *(const float4*)(sc + j + 4);
        *(float4*)shv       = *(const float4*)(sh + j);
        *(float4*)(shv + 4) = *(const float4*)(sh + j + 4);
#pragma unroll
        for (int i = 0; i < 8; i++)
            v[i] = fmaxf(fmaf(gv[i] + cv[i], scv[i], shv[i]), 0.f);
        uint4 h, l; split_pack8(v, h, l);
        *(uint4*)(hi + bo + j * 2) = h;
        *(uint4*)(lo + bo + j * 2) = l;
    }
}

// mainloop chunk: 3-term split MMA, warp tile 64x32, tiles 144B row stride.
// Term-major issue order: dependent mmas on the same accumulator are separated
// by 8 independent ones (accumulator RAW-stall relief).
__device__ __forceinline__ void mma_chunk(uint32_t aAh, uint32_t aAl,
                                          uint32_t aBh, uint32_t aBl,
                                          float acc[4][4][4]) {
#pragma unroll
    for (int ks = 0; ks < 4; ks++) {
        uint32_t bh[2][4], bl[2][4];
        ldsm4(bh[0], aBh + ks * 32);
        ldsm4(bh[1], aBh + 16 * 144 + ks * 32);
        ldsm4(bl[0], aBl + ks * 32);
        ldsm4(bl[1], aBl + 16 * 144 + ks * 32);
#pragma unroll
        for (int mh = 0; mh < 2; mh++) {
            uint32_t ah[2][4], al[2][4];
            ldsm4(ah[0], aAh + (2 * mh) * 16 * 144 + ks * 32);
            ldsm4(ah[1], aAh + (2 * mh + 1) * 16 * 144 + ks * 32);
            ldsm4(al[0], aAl + (2 * mh) * 16 * 144 + ks * 32);
            ldsm4(al[1], aAl + (2 * mh + 1) * 16 * 144 + ks * 32);
#pragma unroll
            for (int u = 0; u < 2; u++)
#pragma unroll
                for (int j = 0; j < 4; j++)
                    mma16816(acc[2 * mh + u][j], ah[u], &bh[j >> 1][(j & 1) * 2]);
#pragma unroll
            for (int u = 0; u < 2; u++)
#pragma unroll
                for (int j = 0; j < 4; j++)
                    mma16816(acc[2 * mh + u][j], al[u], &bh[j >> 1][(j & 1) * 2]);
#pragma unroll
            for (int u = 0; u < 2; u++)
#pragma unroll
                for (int j = 0; j < 4; j++)
                    mma16816(acc[2 * mh + u][j], ah[u], &bl[j >> 1][(j & 1) * 2]);
        }
    }
}

// ---------------- GC GEMM: fully async, double-buffered ----------------------
#define GC_ST 110592u
#define GC_SMEM (2u * GC_ST)

template <int K, int NOUT>
__global__ __launch_bounds__(512, 1) void k_hmma_gc(
    const __nv_bfloat16* __restrict__ Ah, const __nv_bfloat16* __restrict__ Al,
    const __nv_bfloat16* __restrict__ Wh, const __nv_bfloat16* __restrict__ Wl,
    float* __restrict__ Gout, float* __restrict__ Cout)
{
    extern __shared__ __align__(16) char smem[];
    const int tid = threadIdx.x, wid = tid >> 5, lane = tid & 31;
    const int wm = (wid & 3) * 64, wn = (wid >> 2) * 32;
    const int g = lane >> 2, tig = lane & 3;
    const int mt = blockIdx.y * 256, nt = blockIdx.x * 128;
    const int NCH = K / 64;
    uint32_t sb = s2u(smem);

    auto loadAW = [&](int ch, int s) {
        int kb = ch * 64;
        uint32_t base = sb + (uint32_t)s * GC_ST;
#pragma unroll
        for (int i = 0; i < 8; i++) {
            int seg = tid + i * 512;
            int part = seg >> 11, rem = seg & 2047;
            int row = rem >> 3, sg = rem & 7;
            const __nv_bfloat16* src = (part ? Al : Ah)
                + (size_t)(mt + row) * K + kb + sg * 8;
            cpa16(base + (uint32_t)part * 36864u + row * 144 + sg * 16, src);
        }
#pragma unroll
        for (int i = 0; i < 4; i++) {
            int seg = tid + i * 512;
            int part = seg >> 10, rem = seg & 1023;
            int row = rem >> 3, sg = rem & 7;
            const __nv_bfloat16* src = (part ? Wl : Wh)
                + (size_t)(nt + row) * K + kb + sg * 8;
            cpa16(base + 73728u + (uint32_t)part * 18432u + row * 144 + sg * 16, src);
        }
    };

    const uint32_t offA = (wm + ((lane >> 3) & 1) * 8 + (lane & 7)) * 144
                        + ((lane >> 4) * 8) * 2;
    const uint32_t offB = (wn + (lane >> 4) * 8 + (lane & 7)) * 144
                        + ((lane >> 3) & 1) * 16;

    float acc[4][4][4];
#pragma unroll
    for (int mi = 0; mi < 4; mi++)
#pragma unroll
        for (int j = 0; j < 4; j++)
#pragma unroll
            for (int t = 0; t < 4; t++) acc[mi][j][t] = 0.f;

    loadAW(0, 0); CP_COMMIT();
    loadAW(1, 1); CP_COMMIT();
#pragma unroll 1
    for (int ch = 0; ch < NCH; ch++) {
        if (ch + 1 < NCH) CP_WAIT1(); else CP_WAIT0();
        __syncthreads();
        uint32_t base = sb + (uint32_t)(ch & 1) * GC_ST;
        mma_chunk(base + offA, base + 36864u + offA,
                  base + 73728u + offB, base + 92160u + offB, acc);
        __syncthreads();
        if (ch + 2 < NCH) { loadAW(ch + 2, ch & 1); CP_COMMIT(); }
    }

    float* dstM = (nt >= NOUT) ? Cout : Gout;
    int ocb = nt - ((nt >= NOUT) ? NOUT : 0) + wn;
#pragma unroll
    for (int mi = 0; mi < 4; mi++) {
        int r0 = mt + wm + mi * 16 + g;
#pragma unroll
        for (int j = 0; j < 4; j++) {
            int oc = ocb + j * 8 + 2 * tig;
            *(float2*)&dstM[(size_t)r0 * NOUT + oc] =
                make_float2(acc[mi][j][0], acc[mi][j][1]);
            *(float2*)&dstM[(size_t)(r0 + 8) * NOUT + oc] =
                make_float2(acc[mi][j][2], acc[mi][j][3]);
        }
    }
}

// ---------------- fused layer-2: G staged via cp.async, W double-buffered ----
#define L2_SC   0u
#define L2_SH   4096u
#define L2_IDX  8192u
#define L2_GST  9216u            /* 256 rows x 272 B = 69632 */
#define L2_AH   78848u
#define L2_AL   115712u
#define L2_W(s) (152576u + (uint32_t)(s) * 36864u)
#define L2_SMEM 226304u

template <int D>
__global__ __launch_bounds__(512, 1) void k_hmma_l2(
    const float* __restrict__ Gm, const float* __restrict__ Cm,
    const __nv_bfloat16* __restrict__ W2h, const __nv_bfloat16* __restrict__ W2l,
    const float* __restrict__ scale1, const float* __restrict__ shift1,
    float* sum2, float* sq2)
{
    extern __shared__ __align__(16) char smem[];
    const int tid = threadIdx.x, wid = tid >> 5, lane = tid & 31;
    const int wm = (wid & 3) * 64, wn = (wid >> 2) * 32;
    const int g = lane >> 2, tig = lane & 3;
    const int gbase = blockIdx.y * 32;
    const int nt = blockIdx.x * 128;
    const int NCH = D / 64;
    uint32_t sb = s2u(smem);

    float* s_sc = (float*)(smem + L2_SC);
    float* s_sh = (float*)(smem + L2_SH);
    int* s_idx = (int*)(smem + L2_IDX);
    for (int i = tid; i < D; i += 512) { s_sc[i] = scale1[i]; s_sh[i] = shift1[i]; }
    if (tid < 256) {
        int gg = gbase + (tid >> 3);
        s_idx[tid] = (gg & ~1023) + d_knn[gg * 8 + (tid & 7)];
    }
    __syncthreads();

    auto loadG = [&](int ch) {
        int kb = ch * 64;
#pragma unroll
        for (int i = 0; i < 8; i++) {
            int seg = tid + i * 512;
            int row = seg >> 4, sg = seg & 15;
            const float* src = Gm + (size_t)s_idx[row] * D + kb + sg * 4;
            cpa16(sb + L2_GST + row * 272 + sg * 16, src);
        }
    };
    auto loadW = [&](int ch, int s) {
        int kb = ch * 64;
#pragma unroll
        for (int i = 0; i < 4; i++) {
            int seg = tid + i * 512;
            int part = seg >> 10, rem = seg & 1023;
            int row = rem >> 3, sg = rem & 7;
            const __nv_bfloat16* src = (part ? W2l : W2h)
                + (size_t)(nt + row) * D + kb + sg * 8;
            cpa16(sb + L2_W(s) + (uint32_t)part * 18432u + row * 144 + sg * 16, src);
        }
    };

    const uint32_t offA = (wm + ((lane >> 3) & 1) * 8 + (lane & 7)) * 144
                        + ((lane >> 4) * 8) * 2;
    const uint32_t offB = (wn + (lane >> 4) * 8 + (lane & 7)) * 144
                        + ((lane >> 3) & 1) * 16;

    float acc[4][4][4];
#pragma unroll
    for (int mi = 0; mi < 4; mi++)
#pragma unroll
        for (int j = 0; j < 4; j++)
#pragma unroll
            for (int t = 0; t < 4; t++) acc[mi][j][t] = 0.f;

    const int arow = tid >> 1, half = tid & 1;
    const uint32_t abo = (uint32_t)arow * 144 + (uint32_t)half * 64;
    const float* crow0 = Cm + (size_t)(gbase + (arow >> 3)) * D + half * 32;
    const float* gstp = (const float*)(smem + L2_GST + arow * 272 + half * 128);

    loadW(0, 0); CP_COMMIT();
    loadG(0);    CP_COMMIT();
    loadW(1, 1); CP_COMMIT();
#pragma unroll 1
    for (int ch = 0; ch < NCH; ch++) {
        int kb = ch * 64;
        if (ch + 1 < NCH) CP_WAIT1(); else CP_WAIT0();
        __syncthreads();
        fill_bn(gstp, crow0 + kb, s_sc + kb + half * 32, s_sh + kb + half * 32,
                smem + L2_AH, smem + L2_AL, abo);
        __syncthreads();
        if (ch + 1 < NCH) { loadG(ch + 1); CP_COMMIT(); }
        uint32_t wbase = L2_W(ch & 1);
        mma_chunk(sb + L2_AH + offA, sb + L2_AL + offA,
                  sb + wbase + offB, sb + wbase + 18432u + offB, acc);
        __syncthreads();
        if (ch + 2 < NCH) { loadW(ch + 2, ch & 1); CP_COMMIT(); }
    }

    // epilogue: per-group k-max/min + channel sum/sumsq via lane butterflies
#pragma unroll
    for (int j = 0; j < 4; j++) {
        int colb = nt + wn + j * 8 + 2 * tig;
        float sE = 0.f, sO = 0.f, qE = 0.f, qO = 0.f;
#pragma unroll
        for (int mi = 0; mi < 4; mi++) {
            float v0 = acc[mi][j][0], v1 = acc[mi][j][1];
            float v2 = acc[mi][j][2], v3 = acc[mi][j][3];
            sE += v0 + v2; sO += v1 + v3;
            qE = fmaf(v0, v0, fmaf(v2, v2, qE));
            qO = fmaf(v1, v1, fmaf(v3, v3, qO));
            float mx0 = bflymax(v0), mn0 = bflymin(v0);
            float mx1 = bflymax(v1), mn1 = bflymin(v1);
            float mx2 = bflymax(v2), mn2 = bflymin(v2);
            float mx3 = bflymax(v3), mn3 = bflymin(v3);
            if (g == 0) {
                int grpA = gbase + (wm >> 3) + mi * 2;
                *(float2*)&d_ymax[(size_t)grpA * D + colb] = make_float2(mx0, mx1);
                *(float2*)&d_ymin[(size_t)grpA * D + colb] = make_float2(mn0, mn1);
                *(float2*)&d_ymax[(size_t)(grpA + 1) * D + colb] = make_float2(mx2, mx3);
                *(float2*)&d_ymin[(size_t)(grpA + 1) * D + colb] = make_float2(mn2, mn3);
            }
        }
        sE = bflyadd(sE); sO = bflyadd(sO);
        qE = bflyadd(qE); qO = bflyadd(qO);
        if (g == 0) {
            atomicAdd(&sum2[colb], sE);
            atomicAdd(&sum2[colb + 1], sO);
            atomicAdd(&sq2[colb], qE);
            atomicAdd(&sq2[colb + 1], qO);
        }
    }
}

// ---------------- prep / small kernels ----------------------------------------
__global__ void k_zero2(float* a, float* b, int n) {
    int i = blockIdx.x * 256 + threadIdx.x;
    if (i < n) { a[i] = 0.f; b[i] = 0.f; }
}
__global__ void k_split_w(const float* __restrict__ W, __nv_bfloat16* h, __nv_bfloat16* l,
                          int NOUT, int K) {
    int i = blockIdx.x * 256 + threadIdx.x;
    if (i >= 2 * NOUT * K) return;
    int o = i / K, k = i - o * K;
    float v;
    if (o < NOUT) v = W[(size_t)o * 2 * K + k];
    else {
        const float* r = W + (size_t)(o - NOUT) * 2 * K;
        v = r[K + k] - r[k];
    }
    __nv_bfloat16 hh = __float2bfloat16(v);
    h[i] = hh;
    l[i] = __float2bfloat16(v - __bfloat162float(hh));
}
__global__ void k_split_plain(const float* __restrict__ W, __nv_bfloat16* h,
                              __nv_bfloat16* l, int total) {
    int i = blockIdx.x * 256 + threadIdx.x;
    if (i >= total) return;
    float v = W[i];
    __nv_bfloat16 hh = __float2bfloat16(v);
    h[i] = hh;
    l[i] = __float2bfloat16(v - __bfloat162float(hh));
}

__global__ void k_knn(const float* __restrict__ xyz) {
    __shared__ float sx[1024], sy[1024], sz[1024], sq[1024];
    int b = blockIdx.x >> 2;
    const float* base = xyz + b * 1024 * 3;
    for (int i = threadIdx.x; i < 1024; i += 256) {
        float x = base[i * 3], y = base[i * 3 + 1], z = base[i * 3 + 2];
        sx[i] = x; sy[i] = y; sz[i] = z;
        sq[i] = x * x + y * y + z * z;
    }
    __syncthreads();
    int n = (blockIdx.x & 3) * 256 + threadIdx.x;
    float px = sx[n], py = sy[n], pz = sz[n], pq = sq[n];
    float bd[8]; int bi[8];
#pragma unroll
    for (int j = 0; j < 8; j++) { bd[j] = 3.4e38f; bi[j] = -1; }
    for (int m = 0; m < 1024; m++) {
        float d2 = pq + sq[m] - 2.f * (px * sx[m] + py * sy[m] + pz * sz[m]);
        if (d2 < bd[7]) {
            float nd = d2; int ni = m;
#pragma unroll
            for (int t = 0; t < 8; t++) {
                if (nd < bd[t]) {
                    float td = bd[t]; int ti = bi[t];
                    bd[t] = nd; bi[t] = ni; nd = td; ni = ti;
                }
            }
        }
    }
#pragma unroll
    for (int j = 0; j < 8; j++) d_knn[(b * 1024 + n) * 8 + j] = bi[j];
}

__global__ __launch_bounds__(256) void k_gemm(
    const float* __restrict__ A, int lda, const float* __restrict__ W, int ldw,
    float* __restrict__ Cout, int M, int N, int K, float* sum, float* sq)
{
    __shared__ float As[16][64];
    __shared__ float Ws[16][64];
    int tid = threadIdx.x;
    int mt = blockIdx.y * 64, nt = blockIdx.x * 64;
    int lr = tid >> 2, lk = (tid & 3) * 4;
    int tx = tid & 15, ty = tid >> 4;
    float acc[4][4];
#pragma unroll
    for (int i = 0; i < 4; i++)
#pragma unroll
        for (int j = 0; j < 4; j++) acc[i][j] = 0.f;
    for (int kb = 0; kb < K; kb += 16) {
#pragma unroll
        for (int j = 0; j < 4; j++) {
            int kk = kb + lk + j;
            As[lk + j][lr] = (kk < K) ? A[(mt + lr) * lda + kk] : 0.f;
            Ws[lk + j][lr] = (kk < K) ? W[(nt + lr) * ldw + kk] : 0.f;
        }
        __syncthreads();
#pragma unroll
        for (int kk = 0; kk < 16; kk++) {
            float4 a = *(const float4*)&As[kk][ty * 4];
            float4 w = *(const float4*)&Ws[kk][tx * 4];
            float av[4] = {a.x, a.y, a.z, a.w};
            float wv[4] = {w.x, w.y, w.z, w.w};
#pragma unroll
            for (int i = 0; i < 4; i++)
#pragma unroll
                for (int j = 0; j < 4; j++)
                    acc[i][j] = fmaf(av[i], wv[j], acc[i][j]);
        }
        __syncthreads();
    }
#pragma unroll
    for (int i = 0; i < 4; i++)
        *(float4*)&Cout[(mt + ty * 4 + i) * N + nt + tx * 4] =
            make_float4(acc[i][0], acc[i][1], acc[i][2], acc[i][3]);
    if (sum) {
        float* red = &As[0][0];
        float ps[4], pq[4];
#pragma unroll
        for (int j = 0; j < 4; j++) {
            ps[j] = 0.f; pq[j] = 0.f;
#pragma unroll
            for (int i = 0; i < 4; i++) { ps[j] += acc[i][j]; pq[j] += acc[i][j] * acc[i][j]; }
        }
#pragma unroll
        for (int j = 0; j < 4; j++) red[ty * 64 + tx * 4 + j] = ps[j];
        __syncthreads();
        if (tid < 64) {
            float s = 0.f;
#pragma unroll
            for (int t = 0; t < 16; t++) s += red[t * 64 + tid];
            atomicAdd(&sum[nt + tid], s);
        }
        __syncthreads();
#pragma unroll
        for (int j = 0; j < 4; j++) red[ty * 64 + tx * 4 + j] = pq[j];
        __syncthreads();
        if (tid < 64) {
            float s = 0.f;
#pragma unroll
            for (int t = 0; t < 16; t++) s += red[t * 64 + tid];
            atomicAdd(&sq[nt + tid], s);
        }
    }
}

template <int D>
__global__ void k_stats1(float* sum1, float* sq1) {
    __shared__ int sidx[64];
    int d = blockIdx.x * 128 + threadIdx.x;
    int gbase = blockIdx.y * 8;
    if (threadIdx.x < 64) {
        int g = gbase + (threadIdx.x >> 3);
        sidx[threadIdx.x] = (g & ~1023) + d_knn[g * 8 + (threadIdx.x & 7)];
    }
    __syncthreads();
    float s = 0.f, ss = 0.f;
#pragma unroll
    for (int gi = 0; gi < 8; gi++) {
        float c = d_C[(size_t)(gbase + gi) * D + d];
#pragma unroll
        for (int kk = 0; kk < 8; kk++) {
            float x = d_G[(size_t)sidx[gi * 8 + kk] * D + d] + c;
            s += x; ss += x * x;
        }
    }
    atomicAdd(&sum1[d], s);
    atomicAdd(&sq1[d], ss);
}

__global__ void k_finalize(const float* sum, const float* sq,
                           const float* g, const float* b,
                           float* scale, float* shift, int nch, float invcnt) {
    int c = blockIdx.x * 256 + threadIdx.x;
    if (c >= nch) return;
    float m = sum[c] * invcnt;
    float v = sq[c] * invcnt - m * m;
    float s = rsqrtf(v + EPSV) * g[c];
    scale[c] = s;
    shift[c] = b[c] - m * s;
}

__global__ void k_apply(float* x, const float* scale, const float* shift,
                        int total, int cmask) {
    int i = blockIdx.x * 256 + threadIdx.x;
    if (i >= total) return;
    int c = i & cmask;
    x[i] = fmaxf(fmaf(x[i], scale[c], shift[c]), 0.f);
}
__global__ void k_apply_split(const float* __restrict__ x, const float* scale,
                              const float* shift, __nv_bfloat16* h, __nv_bfloat16* l,
                              int total, int cmask) {
    int i = blockIdx.x * 256 + threadIdx.x;
    if (i >= total) return;
    int c = i & cmask;
    float v = fmaxf(fmaf(x[i], scale[c], shift[c]), 0.f);
    __nv_bfloat16 hh = __float2bfloat16(v);
    h[i] = hh;
    l[i] = __float2bfloat16(v - __bfloat162float(hh));
}
__global__ void k_apply_sel_split(const float* __restrict__ ymax,
                                  const float* __restrict__ ymin,
                                  const float* scale, const float* shift,
                                  __nv_bfloat16* h, __nv_bfloat16* l,
                                  int total, int cmask) {
    int i = blockIdx.x * 256 + threadIdx.x;
    if (i >= total) return;
    int c = i & cmask;
    float s = scale[c];
    float v0 = (s >= 0.f) ? ymax[i] : ymin[i];
    float v = fmaxf(fmaf(v0, s, shift[c]), 0.f);
    __nv_bfloat16 hh = __float2bfloat16(v);
    h[i] = hh;
    l[i] = __float2bfloat16(v - __bfloat162float(hh));
}

__global__ void k_final(const float* __restrict__ scale, const float* __restrict__ shift,
                        float* __restrict__ out) {
    __shared__ float t[32][33];
    int b = blockIdx.z;
    int nt = blockIdx.y * 32, otb = blockIdx.x * 32;
    int n = nt + threadIdx.y, o = otb + threadIdx.x;
    int p = b * 1024 + n;
    float s = scale[o];
    float v = (s >= 0.f) ? d_ymax[(size_t)p * 1024 + o] : d_ymin[(size_t)p * 1024 + o];
    t[threadIdx.y][threadIdx.x] = fmaxf(fmaf(v, s, shift[o]), 0.f);
    __syncthreads();
    out[b * 1048576 + (otb + threadIdx.y) * 1024 + nt + threadIdx.x] =
        t[threadIdx.x][threadIdx.y];
}

// ---------------- launch ------------------------------------------------------
extern "C" void kernel_launch(void* const* d_in, const int* in_sizes, int n_in,
                              void* d_out, int out_size) {
    const float* xyz = (const float*)d_in[0];
    const float* W1  = (const float*)d_in[1];
    const float* g1  = (const float*)d_in[2];
    const float* b1  = (const float*)d_in[3];
    const float* W2  = (const float*)d_in[4];
    const float* g2  = (const float*)d_in[5];
    const float* b2  = (const float*)d_in[6];
    const float* WA1 = (const float*)d_in[7];
    const float* gA1 = (const float*)d_in[8];
    const float* bA1 = (const float*)d_in[9];
    const float* WA2 = (const float*)d_in[10];
    const float* gA2 = (const float*)d_in[11];
    const float* bA2 = (const float*)d_in[12];
    const float* WB1 = (const float*)d_in[13];
    const float* gB1 = (const float*)d_in[14];
    const float* bB1 = (const float*)d_in[15];
    const float* WB2 = (const float*)d_in[16];
    const float* gB2 = (const float*)d_in[17];
    const float* bB2 = (const float*)d_in[18];
    float* out = (float*)d_out;

    float *h1, *h2, *G, *C, *sum, *sq, *scale, *shift, *ymx, *ymn;
    cudaGetSymbolAddress((void**)&h1, d_h1);
    cudaGetSymbolAddress((void**)&h2, d_h2);
    cudaGetSymbolAddress((void**)&G, d_G);
    cudaGetSymbolAddress((void**)&C, d_C);
    cudaGetSymbolAddress((void**)&sum, d_sum);
    cudaGetSymbolAddress((void**)&sq, d_sq);
    cudaGetSymbolAddress((void**)&scale, d_scale);
    cudaGetSymbolAddress((void**)&shift, d_shift);
    cudaGetSymbolAddress((void**)&ymx, d_ymax);
    cudaGetSymbolAddress((void**)&ymn, d_ymin);
    __nv_bfloat16 *h2h, *h2l, *lAh, *lAl, *wA1h, *wA1l, *wB1h, *wB1l,
                  *wA2h, *wA2l, *wB2h, *wB2l;
    cudaGetSymbolAddress((void**)&h2h, d_h2h);
    cudaGetSymbolAddress((void**)&h2l, d_h2l);
    cudaGetSymbolAddress((void**)&lAh, d_lAh);
    cudaGetSymbolAddress((void**)&lAl, d_lAl);
    cudaGetSymbolAddress((void**)&wA1h, d_wA1h);
    cudaGetSymbolAddress((void**)&wA1l, d_wA1l);
    cudaGetSymbolAddress((void**)&wB1h, d_wB1h);
    cudaGetSymbolAddress((void**)&wB1l, d_wB1l);
    cudaGetSymbolAddress((void**)&wA2h, d_wA2h);
    cudaGetSymbolAddress((void**)&wA2l, d_wA2l);
    cudaGetSymbolAddress((void**)&wB2h, d_wB2h);
    cudaGetSymbolAddress((void**)&wB2l, d_wB2l);

    cudaFuncSetAttribute(k_hmma_gc<256, 512>,
                         cudaFuncAttributeMaxDynamicSharedMemorySize, GC_SMEM);
    cudaFuncSetAttribute(k_hmma_gc<512, 1024>,
                         cudaFuncAttributeMaxDynamicSharedMemorySize, GC_SMEM);
    cudaFuncSetAttribute(k_hmma_l2<512>,
                         cudaFuncAttributeMaxDynamicSharedMemorySize, L2_SMEM);
    cudaFuncSetAttribute(k_hmma_l2<1024>,
                         cudaFuncAttributeMaxDynamicSharedMemorySize, L2_SMEM);

    k_zero2<<<24, 256>>>(sum, sq, 6 * 1024);
    k_knn<<<32, 256>>>(xyz);

    // weight splits (cheap, bandwidth-bound)
    k_split_w<<<1024, 256>>>(WA1, wA1h, wA1l, 512, 256);
    k_split_w<<<4096, 256>>>(WB1, wB1h, wB1l, 1024, 512);
    k_split_plain<<<1024, 256>>>(WA2, wA2h, wA2l, 512 * 512);
    k_split_plain<<<4096, 256>>>(WB2, wB2h, wB2l, 1024 * 1024);

    // stage 0 (FFMA, tiny)
    k_gemm<<<dim3(1, 128), 256>>>(xyz, 3, W1, 3, h1, NPTS, 64, 3, sum, sq);
    k_finalize<<<1, 256>>>(sum, sq, g1, b1, scale, shift, 64, 1.f / NPTS);
    k_apply<<<NPTS * 64 / 256, 256>>>(h1, scale, shift, NPTS * 64, 63);
    k_gemm<<<dim3(4, 128), 256>>>(h1, 64, W2, 64, h2, NPTS, 256, 64,
                                  sum + 1024, sq + 1024);
    k_finalize<<<1, 256>>>(sum + 1024, sq + 1024, g2, b2, scale + 1024, shift + 1024,
                           256, 1.f / NPTS);
    k_apply_split<<<NPTS * 256 / 256, 256>>>(h2, scale + 1024, shift + 1024,
                                             h2h, h2l, NPTS * 256, 255);

    // stage A
    k_hmma_gc<256, 512><<<dim3(8, 32), 512, GC_SMEM>>>(h2h, h2l, wA1h, wA1l, G, C);
    k_stats1<512><<<dim3(4, NPTS / 8), 128>>>(sum + 2048, sq + 2048);
    k_finalize<<<2, 256>>>(sum + 2048, sq + 2048, gA1, bA1, scale + 2048, shift + 2048,
                           512, 1.f / 65536.f);
    k_hmma_l2<512><<<dim3(4, 256), 512, L2_SMEM>>>(G, C, wA2h, wA2l,
                                                   scale + 2048, shift + 2048,
                                                   sum + 3072, sq + 3072);
    k_finalize<<<2, 256>>>(sum + 3072, sq + 3072, gA2, bA2, scale + 3072, shift + 3072,
                           512, 1.f / 65536.f);
    k_apply_sel_split<<<NPTS * 512 / 256, 256>>>(ymx, ymn, scale + 3072, shift + 3072,
                                                 lAh, lAl, NPTS * 512, 511);

    // stage B
    k_hmma_gc<512, 1024><<<dim3(16, 32), 512, GC_SMEM>>>(lAh, lAl, wB1h, wB1l, G, C);
    k_stats1<1024><<<dim3(8, NPTS / 8), 128>>>(sum + 4096, sq + 4096);
    k_finalize<<<4, 256>>>(sum + 4096, sq + 4096, gB1, bB1, scale + 4096, shift + 4096,
                           1024, 1.f / 65536.f);
    k_hmma_l2<1024><<<dim3(8, 256), 512, L2_SMEM>>>(G, C, wB2h, wB2l,
                                                    scale + 4096, shift + 4096,
                                                    sum + 5120, sq + 5120);
    k_finalize<<<4, 256>>>(sum + 5120, sq + 5120, gB2, bB2, scale + 5120, shift + 5120,
                           1024, 1.f / 65536.f);
    k_final<<<dim3(32, 32, 8), dim3(32, 32)>>>(scale + 5120, shift + 5120, out);
}

// round 16
// speedup vs baseline: 1.2112x; 1.2112x over previous
#include <cuda_runtime.h>
#include <cuda_fp16.h>
#include <math.h>
#include <stdint.h>

#define NPTS 8192
#define EPSV 1e-5f

// fp32 scratch
__device__ float d_h1[NPTS * 64];
__device__ float d_h2[NPTS * 256];
__device__ int   d_knn[NPTS * 8];
__device__ float d_G[NPTS * 1024];
__device__ float d_C[NPTS * 1024];
__device__ float d_ymax[NPTS * 1024];
__device__ float d_ymin[NPTS * 1024];
__device__ float d_sum[6 * 1024];
__device__ float d_sq[6 * 1024];
__device__ float d_scale[6 * 1024];
__device__ float d_shift[6 * 1024];
// fp16 operands: activations split (hi+lo), weights single
__device__ __half d_h2h[NPTS * 256],  d_h2l[NPTS * 256];
__device__ __half d_lAh[NPTS * 512],  d_lAl[NPTS * 512];
__device__ __half d_wA1f[1024 * 256];
__device__ __half d_wB1f[2048 * 512];
__device__ __half d_wA2f[512 * 512];
__device__ __half d_wB2f[1024 * 1024];

// ---------------- helpers ----------------------------------------------------
__device__ __forceinline__ uint32_t s2u(const void* p) {
    uint32_t a;
    asm("{ .reg .u64 t; cvta.to.shared.u64 t, %1; cvt.u32.u64 %0, t; }"
        : "=r"(a) : "l"(p));
    return a;
}
__device__ __forceinline__ void ldsm4(uint32_t* r, uint32_t a) {
    asm volatile("ldmatrix.sync.aligned.m8n8.x4.shared.b16 {%0,%1,%2,%3}, [%4];"
                 : "=r"(r[0]), "=r"(r[1]), "=r"(r[2]), "=r"(r[3]) : "r"(a));
}
__device__ __forceinline__ void mma16816(float* c, const uint32_t* a, const uint32_t* b) {
    asm volatile(
        "mma.sync.aligned.m16n8k16.row.col.f32.f16.f16.f32 "
        "{%0,%1,%2,%3}, {%4,%5,%6,%7}, {%8,%9}, {%0,%1,%2,%3};"
        : "+f"(c[0]), "+f"(c[1]), "+f"(c[2]), "+f"(c[3])
        : "r"(a[0]), "r"(a[1]), "r"(a[2]), "r"(a[3]), "r"(b[0]), "r"(b[1]));
}
__device__ __forceinline__ void cpa16(uint32_t dst, const void* src) {
    asm volatile("cp.async.cg.shared.global [%0], [%1], 16;" :: "r"(dst), "l"(src));
}
#define CP_COMMIT() asm volatile("cp.async.commit_group;" ::: "memory")
#define CP_WAIT1() asm volatile("cp.async.wait_group 1;" ::: "memory")
#define CP_WAIT0() asm volatile("cp.async.wait_group 0;" ::: "memory")

__device__ __forceinline__ float bflymax(float v) {
    v = fmaxf(v, __shfl_xor_sync(0xffffffffu, v, 4));
    v = fmaxf(v, __shfl_xor_sync(0xffffffffu, v, 8));
    v = fmaxf(v, __shfl_xor_sync(0xffffffffu, v, 16));
    return v;
}
__device__ __forceinline__ float bflymin(float v) {
    v = fminf(v, __shfl_xor_sync(0xffffffffu, v, 4));
    v = fminf(v, __shfl_xor_sync(0xffffffffu, v, 8));
    v = fminf(v, __shfl_xor_sync(0xffffffffu, v, 16));
    return v;
}
__device__ __forceinline__ float bflyadd(float v) {
    v += __shfl_xor_sync(0xffffffffu, v, 4);
    v += __shfl_xor_sync(0xffffffffu, v, 8);
    v += __shfl_xor_sync(0xffffffffu, v, 16);
    return v;
}

__device__ __forceinline__ void split_pack8h(const float* v, uint4& h, uint4& l) {
    uint32_t hh[4], ll[4];
#pragma unroll
    for (int i = 0; i < 4; i++) {
        __half2 hp = __floats2half2_rn(v[2 * i], v[2 * i + 1]);
        float r0 = v[2 * i] - __half2float(__low2half(hp));
        float r1 = v[2 * i + 1] - __half2float(__high2half(hp));
        __half2 lp = __floats2half2_rn(r0, r1);
        hh[i] = reinterpret_cast<uint32_t&>(hp);
        ll[i] = reinterpret_cast<uint32_t&>(lp);
    }
    h = make_uint4(hh[0], hh[1], hh[2], hh[3]);
    l = make_uint4(ll[0], ll[1], ll[2], ll[3]);
}
// BN+ReLU+fp16 split: g may point into SMEM (generic loads)
__device__ __forceinline__ void fill_bn(const float* g, const float* __restrict__ c,
                                        const float* sc, const float* sh,
                                        char* hi, char* lo, uint32_t bo) {
#pragma unroll
    for (int j = 0; j < 32; j += 8) {
        float gv[8], cv[8], scv[8], shv[8], v[8];
        *(float4*)gv        = *(const float4*)(g + j);
        *(float4*)(gv + 4)  = *(const float4*)(g + j + 4);
        *(float4*)cv        = *(const float4*)(c + j);
        *(float4*)(cv + 4)  = *(const float4*)(c + j + 4);
        *(float4*)scv       = *(const float4*)(sc + j);
        *(float4*)(scv + 4) = *(const float4*)(sc + j + 4);
        *(float4*)shv       = *(const float4*)(sh + j);
        *(float4*)(shv + 4) = *(const float4*)(sh + j + 4);
#pragma unroll
        for (int i = 0; i < 8; i++)
            v[i] = fmaxf(fmaf(gv[i] + cv[i], scv[i], shv[i]), 0.f);
        uint4 h, l; split_pack8h(v, h, l);
        *(uint4*)(hi + bo + j * 2) = h;
        *(uint4*)(lo + bo + j * 2) = l;
    }
}

// mainloop chunk: 2-term split MMA (A hi/lo x W single), warp tile 64x32,
// 144B row stride tiles.
__device__ __forceinline__ void mma_chunk(uint32_t aAh, uint32_t aAl, uint32_t aBh,
                                          float acc[4][4][4]) {
#pragma unroll
    for (int ks = 0; ks < 4; ks++) {
        uint32_t bh[2][4];
        ldsm4(bh[0], aBh + ks * 32);
        ldsm4(bh[1], aBh + 16 * 144 + ks * 32);
#pragma unroll
        for (int mh = 0; mh < 2; mh++) {
            uint32_t ah[2][4], al[2][4];
            ldsm4(ah[0], aAh + (2 * mh) * 16 * 144 + ks * 32);
            ldsm4(ah[1], aAh + (2 * mh + 1) * 16 * 144 + ks * 32);
            ldsm4(al[0], aAl + (2 * mh) * 16 * 144 + ks * 32);
            ldsm4(al[1], aAl + (2 * mh + 1) * 16 * 144 + ks * 32);
#pragma unroll
            for (int u = 0; u < 2; u++)
#pragma unroll
                for (int j = 0; j < 4; j++)
                    mma16816(acc[2 * mh + u][j], ah[u], &bh[j >> 1][(j & 1) * 2]);
#pragma unroll
            for (int u = 0; u < 2; u++)
#pragma unroll
                for (int j = 0; j < 4; j++)
                    mma16816(acc[2 * mh + u][j], al[u], &bh[j >> 1][(j & 1) * 2]);
        }
    }
}

// ---------------- GC GEMM: fully async, double-buffered ----------------------
// per stage: A(hi,lo) 2x36864 + W 18432 = 92160; x2 stages
#define GC_ST 92160u
#define GC_SMEM (2u * GC_ST)

template <int K, int NOUT>
__global__ __launch_bounds__(512, 1) void k_hmma_gc(
    const __half* __restrict__ Ah, const __half* __restrict__ Al,
    const __half* __restrict__ Wf,
    float* __restrict__ Gout, float* __restrict__ Cout)
{
    extern __shared__ __align__(16) char smem[];
    const int tid = threadIdx.x, wid = tid >> 5, lane = tid & 31;
    const int wm = (wid & 3) * 64, wn = (wid >> 2) * 32;
    const int g = lane >> 2, tig = lane & 3;
    const int mt = blockIdx.y * 256, nt = blockIdx.x * 128;
    const int NCH = K / 64;
    uint32_t sb = s2u(smem);

    auto loadAW = [&](int ch, int s) {
        int kb = ch * 64;
        uint32_t base = sb + (uint32_t)s * GC_ST;
#pragma unroll
        for (int i = 0; i < 8; i++) {             // A: 4096 segs of 16B
            int seg = tid + i * 512;
            int part = seg >> 11, rem = seg & 2047;
            int row = rem >> 3, sg = rem & 7;
            const __half* src = (part ? Al : Ah)
                + (size_t)(mt + row) * K + kb + sg * 8;
            cpa16(base + (uint32_t)part * 36864u + row * 144 + sg * 16, src);
        }
#pragma unroll
        for (int i = 0; i < 2; i++) {             // W: 1024 segs
            int seg = tid + i * 512;
            int row = seg >> 3, sg = seg & 7;
            const __half* src = Wf + (size_t)(nt + row) * K + kb + sg * 8;
            cpa16(base + 73728u + row * 144 + sg * 16, src);
        }
    };

    const uint32_t offA = (wm + ((lane >> 3) & 1) * 8 + (lane & 7)) * 144
                        + ((lane >> 4) * 8) * 2;
    const uint32_t offB = (wn + (lane >> 4) * 8 + (lane & 7)) * 144
                        + ((lane >> 3) & 1) * 16;

    float acc[4][4][4];
#pragma unroll
    for (int mi = 0; mi < 4; mi++)
#pragma unroll
        for (int j = 0; j < 4; j++)
#pragma unroll
            for (int t = 0; t < 4; t++) acc[mi][j][t] = 0.f;

    loadAW(0, 0); CP_COMMIT();
    loadAW(1, 1); CP_COMMIT();
#pragma unroll 1
    for (int ch = 0; ch < NCH; ch++) {
        if (ch + 1 < NCH) CP_WAIT1(); else CP_WAIT0();
        __syncthreads();
        uint32_t base = sb + (uint32_t)(ch & 1) * GC_ST;
        mma_chunk(base + offA, base + 36864u + offA, base + 73728u + offB, acc);
        __syncthreads();
        if (ch + 2 < NCH) { loadAW(ch + 2, ch & 1); CP_COMMIT(); }
    }

    float* dstM = (nt >= NOUT) ? Cout : Gout;
    int ocb = nt - ((nt >= NOUT) ? NOUT : 0) + wn;
#pragma unroll
    for (int mi = 0; mi < 4; mi++) {
        int r0 = mt + wm + mi * 16 + g;
#pragma unroll
        for (int j = 0; j < 4; j++) {
            int oc = ocb + j * 8 + 2 * tig;
            *(float2*)&dstM[(size_t)r0 * NOUT + oc] =
                make_float2(acc[mi][j][0], acc[mi][j][1]);
            *(float2*)&dstM[(size_t)(r0 + 8) * NOUT + oc] =
                make_float2(acc[mi][j][2], acc[mi][j][3]);
        }
    }
}

// ---------------- fused layer-2: G staged via cp.async, W double-buffered ----
#define L2_SC   0u
#define L2_SH   4096u
#define L2_IDX  8192u
#define L2_GST  9216u            /* 256 rows x 272 B = 69632 */
#define L2_AH   78848u
#define L2_AL   115712u
#define L2_W(s) (152576u + (uint32_t)(s) * 18432u)
#define L2_SMEM 189440u

template <int D>
__global__ __launch_bounds__(512, 1) void k_hmma_l2(
    const float* __restrict__ Gm, const float* __restrict__ Cm,
    const __half* __restrict__ W2f,
    const float* __restrict__ scale1, const float* __restrict__ shift1,
    float* sum2, float* sq2)
{
    extern __shared__ __align__(16) char smem[];
    const int tid = threadIdx.x, wid = tid >> 5, lane = tid & 31;
    const int wm = (wid & 3) * 64, wn = (wid >> 2) * 32;
    const int g = lane >> 2, tig = lane & 3;
    const int gbase = blockIdx.y * 32;
    const int nt = blockIdx.x * 128;
    const int NCH = D / 64;
    uint32_t sb = s2u(smem);

    float* s_sc = (float*)(smem + L2_SC);
    float* s_sh = (float*)(smem + L2_SH);
    int* s_idx = (int*)(smem + L2_IDX);
    for (int i = tid; i < D; i += 512) { s_sc[i] = scale1[i]; s_sh[i] = shift1[i]; }
    if (tid < 256) {
        int gg = gbase + (tid >> 3);
        s_idx[tid] = (gg & ~1023) + d_knn[gg * 8 + (tid & 7)];
    }
    __syncthreads();

    auto loadG = [&](int ch) {
        int kb = ch * 64;
#pragma unroll
        for (int i = 0; i < 8; i++) {             // 4096 segs of 16B
            int seg = tid + i * 512;
            int row = seg >> 4, sg = seg & 15;
            const float* src = Gm + (size_t)s_idx[row] * D + kb + sg * 4;
            cpa16(sb + L2_GST + row * 272 + sg * 16, src);
        }
    };
    auto loadW = [&](int ch, int s) {
        int kb = ch * 64;
#pragma unroll
        for (int i = 0; i < 2; i++) {
            int seg = tid + i * 512;
            int row = seg >> 3, sg = seg & 7;
            const __half* src = W2f + (size_t)(nt + row) * D + kb + sg * 8;
            cpa16(sb + L2_W(s) + row * 144 + sg * 16, src);
        }
    };

    const uint32_t offA = (wm + ((lane >> 3) & 1) * 8 + (lane & 7)) * 144
                        + ((lane >> 4) * 8) * 2;
    const uint32_t offB = (wn + (lane >> 4) * 8 + (lane & 7)) * 144
                        + ((lane >> 3) & 1) * 16;

    float acc[4][4][4];
#pragma unroll
    for (int mi = 0; mi < 4; mi++)
#pragma unroll
        for (int j = 0; j < 4; j++)
#pragma unroll
            for (int t = 0; t < 4; t++) acc[mi][j][t] = 0.f;

    const int arow = tid >> 1, half = tid & 1;
    const uint32_t abo = (uint32_t)arow * 144 + (uint32_t)half * 64;
    const float* crow0 = Cm + (size_t)(gbase + (arow >> 3)) * D + half * 32;
    const float* gstp = (const float*)(smem + L2_GST + arow * 272 + half * 128);

    loadW(0, 0); CP_COMMIT();
    loadG(0);    CP_COMMIT();
    loadW(1, 1); CP_COMMIT();
#pragma unroll 1
    for (int ch = 0; ch < NCH; ch++) {
        int kb = ch * 64;
        if (ch + 1 < NCH) CP_WAIT1(); else CP_WAIT0();
        __syncthreads();
        fill_bn(gstp, crow0 + kb, s_sc + kb + half * 32, s_sh + kb + half * 32,
                smem + L2_AH, smem + L2_AL, abo);
        __syncthreads();
        if (ch + 1 < NCH) { loadG(ch + 1); CP_COMMIT(); }
        mma_chunk(sb + L2_AH + offA, sb + L2_AL + offA,
                  sb + L2_W(ch & 1) + offB, acc);
        __syncthreads();
        if (ch + 2 < NCH) { loadW(ch + 2, ch & 1); CP_COMMIT(); }
    }

    // epilogue: per-group k-max/min + channel sum/sumsq via lane butterflies
#pragma unroll
    for (int j = 0; j < 4; j++) {
        int colb = nt + wn + j * 8 + 2 * tig;
        float sE = 0.f, sO = 0.f, qE = 0.f, qO = 0.f;
#pragma unroll
        for (int mi = 0; mi < 4; mi++) {
            float v0 = acc[mi][j][0], v1 = acc[mi][j][1];
            float v2 = acc[mi][j][2], v3 = acc[mi][j][3];
            sE += v0 + v2; sO += v1 + v3;
            qE = fmaf(v0, v0, fmaf(v2, v2, qE));
            qO = fmaf(v1, v1, fmaf(v3, v3, qO));
            float mx0 = bflymax(v0), mn0 = bflymin(v0);
            float mx1 = bflymax(v1), mn1 = bflymin(v1);
            float mx2 = bflymax(v2), mn2 = bflymin(v2);
            float mx3 = bflymax(v3), mn3 = bflymin(v3);
            if (g == 0) {
                int grpA = gbase + (wm >> 3) + mi * 2;
                *(float2*)&d_ymax[(size_t)grpA * D + colb] = make_float2(mx0, mx1);
                *(float2*)&d_ymin[(size_t)grpA * D + colb] = make_float2(mn0, mn1);
                *(float2*)&d_ymax[(size_t)(grpA + 1) * D + colb] = make_float2(mx2, mx3);
                *(float2*)&d_ymin[(size_t)(grpA + 1) * D + colb] = make_float2(mn2, mn3);
            }
        }
        sE = bflyadd(sE); sO = bflyadd(sO);
        qE = bflyadd(qE); qO = bflyadd(qO);
        if (g == 0) {
            atomicAdd(&sum2[colb], sE);
            atomicAdd(&sum2[colb + 1], sO);
            atomicAdd(&sq2[colb], qE);
            atomicAdd(&sq2[colb + 1], qO);
        }
    }
}

// ---------------- prep / small kernels ----------------------------------------
__global__ void k_zero2(float* a, float* b, int n) {
    int i = blockIdx.x * 256 + threadIdx.x;
    if (i < n) { a[i] = 0.f; b[i] = 0.f; }
}
// W -> fp16: rows [0,NOUT): W[o][0:K]; rows [NOUT,2N): W[o-NOUT][K:2K] - W[o-NOUT][0:K]
__global__ void k_conv_w(const float* __restrict__ W, __half* h, int NOUT, int K) {
    int i = blockIdx.x * 256 + threadIdx.x;
    if (i >= 2 * NOUT * K) return;
    int o = i / K, k = i - o * K;
    float v;
    if (o < NOUT) v = W[(size_t)o * 2 * K + k];
    else {
        const float* r = W + (size_t)(o - NOUT) * 2 * K;
        v = r[K + k] - r[k];
    }
    h[i] = __float2half_rn(v);
}
__global__ void k_conv_plain(const float* __restrict__ W, __half* h, int total) {
    int i = blockIdx.x * 256 + threadIdx.x;
    if (i >= total) return;
    h[i] = __float2half_rn(W[i]);
}

__global__ void k_knn(const float* __restrict__ xyz) {
    __shared__ float sx[1024], sy[1024], sz[1024], sq[1024];
    int b = blockIdx.x >> 2;
    const float* base = xyz + b * 1024 * 3;
    for (int i = threadIdx.x; i < 1024; i += 256) {
        float x = base[i * 3], y = base[i * 3 + 1], z = base[i * 3 + 2];
        sx[i] = x; sy[i] = y; sz[i] = z;
        sq[i] = x * x + y * y + z * z;
    }
    __syncthreads();
    int n = (blockIdx.x & 3) * 256 + threadIdx.x;
    float px = sx[n], py = sy[n], pz = sz[n], pq = sq[n];
    float bd[8]; int bi[8];
#pragma unroll
    for (int j = 0; j < 8; j++) { bd[j] = 3.4e38f; bi[j] = -1; }
    for (int m = 0; m < 1024; m++) {
        float d2 = pq + sq[m] - 2.f * (px * sx[m] + py * sy[m] + pz * sz[m]);
        if (d2 < bd[7]) {
            float nd = d2; int ni = m;
#pragma unroll
            for (int t = 0; t < 8; t++) {
                if (nd < bd[t]) {
                    float td = bd[t]; int ti = bi[t];
                    bd[t] = nd; bi[t] = ni; nd = td; ni = ti;
                }
            }
        }
    }
#pragma unroll
    for (int j = 0; j < 8; j++) d_knn[(b * 1024 + n) * 8 + j] = bi[j];
}

__global__ __launch_bounds__(256) void k_gemm(
    const float* __restrict__ A, int lda, const float* __restrict__ W, int ldw,
    float* __restrict__ Cout, int M, int N, int K, float* sum, float* sq)
{
    __shared__ float As[16][64];
    __shared__ float Ws[16][64];
    int tid = threadIdx.x;
    int mt = blockIdx.y * 64, nt = blockIdx.x * 64;
    int lr = tid >> 2, lk = (tid & 3) * 4;
    int tx = tid & 15, ty = tid >> 4;
    float acc[4][4];
#pragma unroll
    for (int i = 0; i < 4; i++)
#pragma unroll
        for (int j = 0; j < 4; j++) acc[i][j] = 0.f;
    for (int kb = 0; kb < K; kb += 16) {
#pragma unroll
        for (int j = 0; j < 4; j++) {
            int kk = kb + lk + j;
            As[lk + j][lr] = (kk < K) ? A[(mt + lr) * lda + kk] : 0.f;
            Ws[lk + j][lr] = (kk < K) ? W[(nt + lr) * ldw + kk] : 0.f;
        }
        __syncthreads();
#pragma unroll
        for (int kk = 0; kk < 16; kk++) {
            float4 a = *(const float4*)&As[kk][ty * 4];
            float4 w = *(const float4*)&Ws[kk][tx * 4];
            float av[4] = {a.x, a.y, a.z, a.w};
            float wv[4] = {w.x, w.y, w.z, w.w};
#pragma unroll
            for (int i = 0; i < 4; i++)
#pragma unroll
                for (int j = 0; j < 4; j++)
                    acc[i][j] = fmaf(av[i], wv[j], acc[i][j]);
        }
        __syncthreads();
    }
#pragma unroll
    for (int i = 0; i < 4; i++)
        *(float4*)&Cout[(mt + ty * 4 + i) * N + nt + tx * 4] =
            make_float4(acc[i][0], acc[i][1], acc[i][2], acc[i][3]);
    if (sum) {
        float* red = &As[0][0];
        float ps[4], pq[4];
#pragma unroll
        for (int j = 0; j < 4; j++) {
            ps[j] = 0.f; pq[j] = 0.f;
#pragma unroll
            for (int i = 0; i < 4; i++) { ps[j] += acc[i][j]; pq[j] += acc[i][j] * acc[i][j]; }
        }
#pragma unroll
        for (int j = 0; j < 4; j++) red[ty * 64 + tx * 4 + j] = ps[j];
        __syncthreads();
        if (tid < 64) {
            float s = 0.f;
#pragma unroll
            for (int t = 0; t < 16; t++) s += red[t * 64 + tid];
            atomicAdd(&sum[nt + tid], s);
        }
        __syncthreads();
#pragma unroll
        for (int j = 0; j < 4; j++) red[ty * 64 + tx * 4 + j] = pq[j];
        __syncthreads();
        if (tid < 64) {
            float s = 0.f;
#pragma unroll
            for (int t = 0; t < 16; t++) s += red[t * 64 + tid];
            atomicAdd(&sq[nt + tid], s);
        }
    }
}

template <int D>
__global__ void k_stats1(float* sum1, float* sq1) {
    __shared__ int sidx[64];
    int d = blockIdx.x * 128 + threadIdx.x;
    int gbase = blockIdx.y * 8;
    if (threadIdx.x < 64) {
        int g = gbase + (threadIdx.x >> 3);
        sidx[threadIdx.x] = (g & ~1023) + d_knn[g * 8 + (threadIdx.x & 7)];
    }
    __syncthreads();
    float s = 0.f, ss = 0.f;
#pragma unroll
    for (int gi = 0; gi < 8; gi++) {
        float c = d_C[(size_t)(gbase + gi) * D + d];
#pragma unroll
        for (int kk = 0; kk < 8; kk++) {
            float x = d_G[(size_t)sidx[gi * 8 + kk] * D + d] + c;
            s += x; ss += x * x;
        }
    }
    atomicAdd(&sum1[d], s);
    atomicAdd(&sq1[d], ss);
}

__global__ void k_finalize(const float* sum, const float* sq,
                           const float* g, const float* b,
                           float* scale, float* shift, int nch, float invcnt) {
    int c = blockIdx.x * 256 + threadIdx.x;
    if (c >= nch) return;
    float m = sum[c] * invcnt;
    float v = sq[c] * invcnt - m * m;
    float s = rsqrtf(v + EPSV) * g[c];
    scale[c] = s;
    shift[c] = b[c] - m * s;
}

__global__ void k_apply(float* x, const float* scale, const float* shift,
                        int total, int cmask) {
    int i = blockIdx.x * 256 + threadIdx.x;
    if (i >= total) return;
    int c = i & cmask;
    x[i] = fmaxf(fmaf(x[i], scale[c], shift[c]), 0.f);
}
__global__ void k_apply_split(const float* __restrict__ x, const float* scale,
                              const float* shift, __half* h, __half* l,
                              int total, int cmask) {
    int i = blockIdx.x * 256 + threadIdx.x;
    if (i >= total) return;
    int c = i & cmask;
    float v = fmaxf(fmaf(x[i], scale[c], shift[c]), 0.f);
    __half hh = __float2half_rn(v);
    h[i] = hh;
    l[i] = __float2half_rn(v - __half2float(hh));
}
__global__ void k_apply_sel_split(const float* __restrict__ ymax,
                                  const float* __restrict__ ymin,
                                  const float* scale, const float* shift,
                                  __half* h, __half* l,
                                  int total, int cmask) {
    int i = blockIdx.x * 256 + threadIdx.x;
    if (i >= total) return;
    int c = i & cmask;
    float s = scale[c];
    float v0 = (s >= 0.f) ? ymax[i] : ymin[i];
    float v = fmaxf(fmaf(v0, s, shift[c]), 0.f);
    __half hh = __float2half_rn(v);
    h[i] = hh;
    l[i] = __float2half_rn(v - __half2float(hh));
}

__global__ void k_final(const float* __restrict__ scale, const float* __restrict__ shift,
                        float* __restrict__ out) {
    __shared__ float t[32][33];
    int b = blockIdx.z;
    int nt = blockIdx.y * 32, otb = blockIdx.x * 32;
    int n = nt + threadIdx.y, o = otb + threadIdx.x;
    int p = b * 1024 + n;
    float s = scale[o];
    float v = (s >= 0.f) ? d_ymax[(size_t)p * 1024 + o] : d_ymin[(size_t)p * 1024 + o];
    t[threadIdx.y][threadIdx.x] = fmaxf(fmaf(v, s, shift[o]), 0.f);
    __syncthreads();
    out[b * 1048576 + (otb + threadIdx.y) * 1024 + nt + threadIdx.x] =
        t[threadIdx.x][threadIdx.y];
}

// ---------------- launch ------------------------------------------------------
extern "C" void kernel_launch(void* const* d_in, const int* in_sizes, int n_in,
                              void* d_out, int out_size) {
    const float* xyz = (const float*)d_in[0];
    const float* W1  = (const float*)d_in[1];
    const float* g1  = (const float*)d_in[2];
    const float* b1  = (const float*)d_in[3];
    const float* W2  = (const float*)d_in[4];
    const float* g2  = (const float*)d_in[5];
    const float* b2  = (const float*)d_in[6];
    const float* WA1 = (const float*)d_in[7];
    const float* gA1 = (const float*)d_in[8];
    const float* bA1 = (const float*)d_in[9];
    const float* WA2 = (const float*)d_in[10];
    const float* gA2 = (const float*)d_in[11];
    const float* bA2 = (const float*)d_in[12];
    const float* WB1 = (const float*)d_in[13];
    const float* gB1 = (const float*)d_in[14];
    const float* bB1 = (const float*)d_in[15];
    const float* WB2 = (const float*)d_in[16];
    const float* gB2 = (const float*)d_in[17];
    const float* bB2 = (const float*)d_in[18];
    float* out = (float*)d_out;

    float *h1, *h2, *G, *C, *sum, *sq, *scale, *shift, *ymx, *ymn;
    cudaGetSymbolAddress((void**)&h1, d_h1);
    cudaGetSymbolAddress((void**)&h2, d_h2);
    cudaGetSymbolAddress((void**)&G, d_G);
    cudaGetSymbolAddress((void**)&C, d_C);
    cudaGetSymbolAddress((void**)&sum, d_sum);
    cudaGetSymbolAddress((void**)&sq, d_sq);
    cudaGetSymbolAddress((void**)&scale, d_scale);
    cudaGetSymbolAddress((void**)&shift, d_shift);
    cudaGetSymbolAddress((void**)&ymx, d_ymax);
    cudaGetSymbolAddress((void**)&ymn, d_ymin);
    __half *h2h, *h2l, *lAh, *lAl, *wA1f, *wB1f, *wA2f, *wB2f;
    cudaGetSymbolAddress((void**)&h2h, d_h2h);
    cudaGetSymbolAddress((void**)&h2l, d_h2l);
    cudaGetSymbolAddress((void**)&lAh, d_lAh);
    cudaGetSymbolAddress((void**)&lAl, d_lAl);
    cudaGetSymbolAddress((void**)&wA1f, d_wA1f);
    cudaGetSymbolAddress((void**)&wB1f, d_wB1f);
    cudaGetSymbolAddress((void**)&wA2f, d_wA2f);
    cudaGetSymbolAddress((void**)&wB2f, d_wB2f);

    cudaFuncSetAttribute(k_hmma_gc<256, 512>,
                         cudaFuncAttributeMaxDynamicSharedMemorySize, GC_SMEM);
    cudaFuncSetAttribute(k_hmma_gc<512, 1024>,
                         cudaFuncAttributeMaxDynamicSharedMemorySize, GC_SMEM);
    cudaFuncSetAttribute(k_hmma_l2<512>,
                         cudaFuncAttributeMaxDynamicSharedMemorySize, L2_SMEM);
    cudaFuncSetAttribute(k_hmma_l2<1024>,
                         cudaFuncAttributeMaxDynamicSharedMemorySize, L2_SMEM);

    k_zero2<<<24, 256>>>(sum, sq, 6 * 1024);
    k_knn<<<32, 256>>>(xyz);

    // weight fp16 conversion (cheap, bandwidth-bound)
    k_conv_w<<<1024, 256>>>(WA1, wA1f, 512, 256);
    k_conv_w<<<4096, 256>>>(WB1, wB1f, 1024, 512);
    k_conv_plain<<<1024, 256>>>(WA2, wA2f, 512 * 512);
    k_conv_plain<<<4096, 256>>>(WB2, wB2f, 1024 * 1024);

    // stage 0 (FFMA, tiny)
    k_gemm<<<dim3(1, 128), 256>>>(xyz, 3, W1, 3, h1, NPTS, 64, 3, sum, sq);
    k_finalize<<<1, 256>>>(sum, sq, g1, b1, scale, shift, 64, 1.f / NPTS);
    k_apply<<<NPTS * 64 / 256, 256>>>(h1, scale, shift, NPTS * 64, 63);
    k_gemm<<<dim3(4, 128), 256>>>(h1, 64, W2, 64, h2, NPTS, 256, 64,
                                  sum + 1024, sq + 1024);
    k_finalize<<<1, 256>>>(sum + 1024, sq + 1024, g2, b2, scale + 1024, shift + 1024,
                           256, 1.f / NPTS);
    k_apply_split<<<NPTS * 256 / 256, 256>>>(h2, scale + 1024, shift + 1024,
                                             h2h, h2l, NPTS * 256, 255);

    // stage A
    k_hmma_gc<256, 512><<<dim3(8, 32), 512, GC_SMEM>>>(h2h, h2l, wA1f, G, C);
    k_stats1<512><<<dim3(4, NPTS / 8), 128>>>(sum + 2048, sq + 2048);
    k_finalize<<<2, 256>>>(sum + 2048, sq + 2048, gA1, bA1, scale + 2048, shift + 2048,
                           512, 1.f / 65536.f);
    k_hmma_l2<512><<<dim3(4, 256), 512, L2_SMEM>>>(G, C, wA2f,
                                                   scale + 2048, shift + 2048,
                                                   sum + 3072, sq + 3072);
    k_finalize<<<2, 256>>>(sum + 3072, sq + 3072, gA2, bA2, scale + 3072, shift + 3072,
                           512, 1.f / 65536.f);
    k_apply_sel_split<<<NPTS * 512 / 256, 256>>>(ymx, ymn, scale + 3072, shift + 3072,
                                                 lAh, lAl, NPTS * 512, 511);

    // stage B
    k_hmma_gc<512, 1024><<<dim3(16, 32), 512, GC_SMEM>>>(lAh, lAl, wB1f, G, C);
    k_stats1<1024><<<dim3(8, NPTS / 8), 128>>>(sum + 4096, sq + 4096);
    k_finalize<<<4, 256>>>(sum + 4096, sq + 4096, gB1, bB1, scale + 4096, shift + 4096,
                           1024, 1.f / 65536.f);
    k_hmma_l2<1024><<<dim3(8, 256), 512, L2_SMEM>>>(G, C, wB2f,
                                                    scale + 4096, shift + 4096,
                                                    sum + 5120, sq + 5120);
    k_finalize<<<4, 256>>>(sum + 5120, sq + 5120, gB2, bB2, scale + 5120, shift + 5120,
                           1024, 1.f / 65536.f);
    k_final<<<dim3(32, 32, 8), dim3(32, 32)>>>(scale + 5120, shift + 5120, out);
}